// round 10
// baseline (speedup 1.0000x reference)
#include <cuda_runtime.h>

#define CH     6
#define ICH    3
#define HWSZ   (512 * 512)
#define HW4    (HWSZ / 4)
#define NB     32
#define EPS    1e-5f
#define LOG2E  1.4426950408889634f
#define ITER   4
#define STAGES 3
#define TPB    128

// cp.async 3-stage smem pipeline, 6 CTAs/SM. Each thread handles 4 tiles
// (same p4, batches b0, b0+8, b0+16, b0+24 with b0 in [0,8)).
// Compute is two passes over the smem tile so all 24 x-values are never
// live in registers at once (pass1: layer1 accumulation; pass2: softmax +
// weighted sum with channel re-read). No __syncthreads in the main loop:
// each thread consumes only its own smem slots, cp.async.wait_group orders.

__global__ __launch_bounds__(TPB, 6) void aff_softmax_kernel(
    const float* __restrict__ x,
    const float* __restrict__ w1, const float* __restrict__ b1,
    const float* __restrict__ g1, const float* __restrict__ be1,
    const float* __restrict__ m1, const float* __restrict__ v1,
    const float* __restrict__ w2, const float* __restrict__ b2,
    const float* __restrict__ g2, const float* __restrict__ be2,
    const float* __restrict__ m2, const float* __restrict__ v2,
    float* __restrict__ out)
{
    __shared__ float4 sbuf[STAGES][CH][TPB];
    __shared__ float sW1[ICH][CH], sB1[ICH], sW2[CH][ICH], sB2[CH];

    // ---- per-block fold of BN into conv weights ----
    {
        int t = threadIdx.x;
        if (t < ICH) {
            float inv = g1[t] * rsqrtf(v1[t] + EPS);
            sB1[t] = (b1[t] - m1[t]) * inv + be1[t];
            #pragma unroll
            for (int c = 0; c < CH; c++) sW1[t][c] = w1[t * CH + c] * inv;
        } else if (t >= 32 && t < 32 + CH) {
            int k = t - 32;
            float inv = g2[k] * rsqrtf(v2[k] + EPS);
            sB2[k] = ((b2[k] - m2[k]) * inv + be2[k]) * LOG2E;
            float invl = inv * LOG2E;
            #pragma unroll
            for (int o = 0; o < ICH; o++) sW2[k][o] = w2[k * ICH + o] * invl;
        }
    }
    __syncthreads();

    // ---- hoist weights; layer2 as deltas vs channel 0 (softmax shift) ----
    float rW1[ICH][CH], rB1[ICH];
    float rW2d[CH - 1][ICH], rB2d[CH - 1];
    #pragma unroll
    for (int o = 0; o < ICH; o++) {
        rB1[o] = sB1[o];
        #pragma unroll
        for (int c = 0; c < CH; c++) rW1[o][c] = sW1[o][c];
    }
    #pragma unroll
    for (int k = 1; k < CH; k++) {
        rB2d[k - 1] = sB2[k] - sB2[0];
        #pragma unroll
        for (int o = 0; o < ICH; o++) rW2d[k - 1][o] = sW2[k][o] - sW2[0][o];
    }

    // tid0 in [0, 2^19): p4 = low 16 bits, b0 = high 3 bits (0..7)
    unsigned int tid0 = blockIdx.x * TPB + threadIdx.x;
    unsigned int p4 = tid0 & (HW4 - 1);
    unsigned int b0 = tid0 >> 16;

    const float4* xp = reinterpret_cast<const float4*>(x)
                       + (size_t)b0 * (CH * HW4) + p4;
    float4* op = reinterpret_cast<float4*>(out) + (size_t)b0 * HW4 + p4;
    const size_t xstep = (size_t)(NB / ITER) * CH * HW4;   // batch += 8
    const size_t ostep = (size_t)(NB / ITER) * HW4;

    unsigned int sslot =
        (unsigned int)__cvta_generic_to_shared(&sbuf[0][0][threadIdx.x]);
    const unsigned int cstride = TPB * (unsigned int)sizeof(float4);
    const unsigned int sstride = CH * cstride;

    // ---- prologue: prefetch STAGES-1 tiles ----
    #pragma unroll
    for (int s = 0; s < STAGES - 1; s++) {
        const float4* g = xp + (size_t)s * xstep;
        #pragma unroll
        for (int c = 0; c < CH; c++) {
            asm volatile("cp.async.cg.shared.global [%0], [%1], 16;"
                         :: "r"(sslot + s * sstride + c * cstride),
                            "l"(g + (size_t)c * HW4));
        }
        asm volatile("cp.async.commit_group;");
    }

    #pragma unroll
    for (int it = 0; it < ITER; it++) {
        if (it + STAGES - 1 < ITER) {
            const float4* g = xp + (size_t)(it + STAGES - 1) * xstep;
            int s = (it + STAGES - 1) % STAGES;
            #pragma unroll
            for (int c = 0; c < CH; c++) {
                asm volatile("cp.async.cg.shared.global [%0], [%1], 16;"
                             :: "r"(sslot + s * sstride + c * cstride),
                                "l"(g + (size_t)c * HW4));
            }
        }
        asm volatile("cp.async.commit_group;");
        asm volatile("cp.async.wait_group %0;" :: "n"(STAGES - 1));

        const int cur = it % STAGES;

        // ---- pass 1: layer1 for all 4 pixels, streaming channels ----
        float h1[ICH][4];
        #pragma unroll
        for (int o = 0; o < ICH; o++)
            h1[o][0] = h1[o][1] = h1[o][2] = h1[o][3] = rB1[o];
        #pragma unroll
        for (int c = 0; c < CH; c++) {
            float4 v = sbuf[cur][c][threadIdx.x];
            #pragma unroll
            for (int o = 0; o < ICH; o++) {
                h1[o][0] = fmaf(rW1[o][c], v.x, h1[o][0]);
                h1[o][1] = fmaf(rW1[o][c], v.y, h1[o][1]);
                h1[o][2] = fmaf(rW1[o][c], v.z, h1[o][2]);
                h1[o][3] = fmaf(rW1[o][c], v.w, h1[o][3]);
            }
        }
        #pragma unroll
        for (int o = 0; o < ICH; o++) {
            #pragma unroll
            for (int j = 0; j < 4; j++) h1[o][j] = fmaxf(h1[o][j], 0.0f);
        }

        // ---- pass 2: shifted softmax + weighted sum, re-reading channels ----
        float s0[4], acc[4];
        {
            float4 v0 = sbuf[cur][0][threadIdx.x];
            acc[0] = v0.x; acc[1] = v0.y; acc[2] = v0.z; acc[3] = v0.w;
            s0[0] = s0[1] = s0[2] = s0[3] = 1.0f;   // e0 == 1
        }
        #pragma unroll
        for (int k = 0; k < CH - 1; k++) {
            float4 vk = sbuf[cur][k + 1][threadIdx.x];
            float vx[4] = {vk.x, vk.y, vk.z, vk.w};
            #pragma unroll
            for (int j = 0; j < 4; j++) {
                float hh = rB2d[k];
                #pragma unroll
                for (int o = 0; o < ICH; o++)
                    hh = fmaf(rW2d[k][o], h1[o][j], hh);
                float e;
                asm("ex2.approx.ftz.f32 %0, %1;" : "=f"(e) : "f"(hh));
                s0[j] += e;
                acc[j] = fmaf(vx[j], e, acc[j]);
            }
        }

        float res[4];
        #pragma unroll
        for (int j = 0; j < 4; j++) {
            float r;
            asm("rcp.approx.ftz.f32 %0, %1;" : "=f"(r) : "f"(s0[j]));
            res[j] = acc[j] * r;
        }

        op[(size_t)it * ostep] = make_float4(res[0], res[1], res[2], res[3]);
        xp += 0;  // xp fixed; tiles addressed via it*xstep above
    }
}

extern "C" void kernel_launch(void* const* d_in, const int* in_sizes, int n_in,
                              void* d_out, int out_size)
{
    const float* x   = (const float*)d_in[0];
    const float* w1  = (const float*)d_in[1];
    const float* b1  = (const float*)d_in[2];
    const float* g1  = (const float*)d_in[3];
    const float* be1 = (const float*)d_in[4];
    const float* m1  = (const float*)d_in[5];
    const float* v1  = (const float*)d_in[6];
    const float* w2  = (const float*)d_in[7];
    const float* b2  = (const float*)d_in[8];
    const float* g2  = (const float*)d_in[9];
    const float* be2 = (const float*)d_in[10];
    const float* m2  = (const float*)d_in[11];
    const float* v2  = (const float*)d_in[12];
    float* out = (float*)d_out;

    // (NB/ITER)=8 batch-groups x HW4 positions = 2^19 threads, 4 tiles each
    const unsigned int NT = (unsigned int)(NB / ITER) * HW4;  // 524,288
    dim3 block(TPB);
    dim3 grid(NT / block.x);                                  // 4096 blocks
    aff_softmax_kernel<<<grid, block>>>(x, w1, b1, g1, be1, m1, v1,
                                        w2, b2, g2, be2, m2, v2, out);
}